// round 1
// baseline (speedup 1.0000x reference)
#include <cuda_runtime.h>
#include <math.h>

// ---------------------------------------------------------------------------
// Problem constants (from setup_inputs): b=4, c=128, a=25, h=w=32
//   tokens: M = h*w * b*a = 1024*100 = 102400, D = 256
//   attention: B = 1024 (pixels), N = 100 (b*a), H = 8, hd = 32
//   conv: cin = c*9 = 1152
// ---------------------------------------------------------------------------
#define TOK_M   102400
#define D_MOD   256
#define D_FF    512
#define QKV_N   768
#define BA      100
#define PIX     1024
#define NHEAD   8
#define HDIM    32
#define CCH     128
#define AA      25
#define BB      4

// ------------------------- scratch (static device) -------------------------
__device__ float g_T  [TOK_M * D_MOD];   // sai2token(buffer)           (residual 1)
__device__ float g_PE [TOK_M * D_MOD];   // sai2token(spa_position)
__device__ float g_X  [TOK_M * D_MOD];   // LN1 output; later reused as final token
__device__ float g_QKV[TOK_M * QKV_N];
__device__ float g_AO [TOK_M * D_MOD];   // attention output (pre-proj)
__device__ float g_S2 [TOK_M * D_MOD];   // after proj+residual          (residual 2)
__device__ float g_Y  [TOK_M * D_MOD];   // LN2 output
__device__ float g_FF1[TOK_M * D_FF];

// ---------------------------------------------------------------------------
// Generic SGEMM: C[M,N] = A[M,K] @ B[K,N] (+bias) (+relu) (+resid)
// BM=BN=128, BK=8, 256 threads, 8x8 micro-tile. M%128==0, N%128==0, K%8==0.
// ---------------------------------------------------------------------------
__global__ __launch_bounds__(256) void sgemm128(
    const float* __restrict__ A, const float* __restrict__ B,
    float* __restrict__ C, int M, int N, int K,
    const float* __restrict__ bias, const float* __restrict__ resid, int relu)
{
    __shared__ float Ast[8 * 128];   // [k][m]
    __shared__ float Bs [8 * 128];   // [k][n]
    const int tid = threadIdx.x;
    const int m0 = blockIdx.y * 128;
    const int n0 = blockIdx.x * 128;
    const int tx = tid & 15;         // n direction
    const int ty = tid >> 4;         // m direction

    float acc[8][8];
#pragma unroll
    for (int i = 0; i < 8; i++)
#pragma unroll
        for (int j = 0; j < 8; j++) acc[i][j] = 0.f;

    const int arow = tid >> 1, acol = (tid & 1) * 4;   // A tile load: 128x8
    const int brow = tid >> 5, bcol = (tid & 31) * 4;  // B tile load: 8x128

    for (int k0 = 0; k0 < K; k0 += 8) {
        float4 av = *(const float4*)(A + (size_t)(m0 + arow) * K + k0 + acol);
        float4 bv = *(const float4*)(B + (size_t)(k0 + brow) * N + n0 + bcol);
        Ast[(acol + 0) * 128 + arow] = av.x;
        Ast[(acol + 1) * 128 + arow] = av.y;
        Ast[(acol + 2) * 128 + arow] = av.z;
        Ast[(acol + 3) * 128 + arow] = av.w;
        *(float4*)&Bs[brow * 128 + bcol] = bv;
        __syncthreads();
#pragma unroll
        for (int kk = 0; kk < 8; kk++) {
            float a[8], b[8];
            *(float4*)(a)     = *(const float4*)&Ast[kk * 128 + ty * 8];
            *(float4*)(a + 4) = *(const float4*)&Ast[kk * 128 + ty * 8 + 4];
            *(float4*)(b)     = *(const float4*)&Bs [kk * 128 + tx * 8];
            *(float4*)(b + 4) = *(const float4*)&Bs [kk * 128 + tx * 8 + 4];
#pragma unroll
            for (int i = 0; i < 8; i++)
#pragma unroll
                for (int j = 0; j < 8; j++) acc[i][j] += a[i] * b[j];
        }
        __syncthreads();
    }

#pragma unroll
    for (int i = 0; i < 8; i++) {
        const int m = m0 + ty * 8 + i;
        float v[8];
#pragma unroll
        for (int j = 0; j < 8; j++) {
            const int n = n0 + tx * 8 + j;
            float x = acc[i][j];
            if (bias)  x += bias[n];
            if (relu)  x = fmaxf(x, 0.f);
            if (resid) x += resid[(size_t)m * N + n];
            v[j] = x;
        }
        *(float4*)(C + (size_t)m * N + n0 + tx * 8)     = *(float4*)(v);
        *(float4*)(C + (size_t)m * N + n0 + tx * 8 + 4) = *(float4*)(v + 4);
    }
}

// ---------------------------------------------------------------------------
// sai2token = implicit-im2col 3x3 conv GEMM.
// out[p, ba, d] = sum_{c,k} x[ba, c, i+di-1, j+dj-1] * W[c*9+k, d]
// Block: fixed ba, 128 pixels (4 image rows), 128 d-cols. K loop over c.
// grid = (D/128=2, PIX/128=8, BA=100)
// ---------------------------------------------------------------------------
__global__ __launch_bounds__(256) void conv_kernel(
    const float* __restrict__ src, const float* __restrict__ W,
    float* __restrict__ out)
{
    __shared__ float xs [6 * 32];    // rows i0-1 .. i0+4 of current channel
    __shared__ float Ast[9 * 128];   // [k][m]
    __shared__ float Bs [9 * 128];   // [k][n]
    const int tid = threadIdx.x;
    const int n0 = blockIdx.x * 128;
    const int p0 = blockIdx.y * 128;
    const int ba = blockIdx.z;
    const int b_ = ba / AA, a_ = ba - b_ * AA;
    const int i0 = p0 >> 5;          // multiple of 4
    const int tx = tid & 15, ty = tid >> 4;

    float acc[8][8];
#pragma unroll
    for (int i = 0; i < 8; i++)
#pragma unroll
        for (int j = 0; j < 8; j++) acc[i][j] = 0.f;

    const float* srcb = src + ((size_t)(b_ * CCH) * AA + a_) * PIX;

    for (int c = 0; c < CCH; c++) {
        if (tid < 192) {
            const int r = tid >> 5;
            const int i = i0 - 1 + r;
            const int j = tid & 31;
            xs[tid] = (i >= 0 && i < 32) ? srcb[(size_t)c * (AA * PIX) + i * 32 + j] : 0.f;
        }
        // Bs: 9x128 = 288 float4 loads
        for (int idx = tid; idx < 288; idx += 256) {
            const int k = idx >> 5, n4 = (idx & 31) * 4;
            *(float4*)&Bs[k * 128 + n4] = *(const float4*)&W[(size_t)(c * 9 + k) * D_MOD + n0 + n4];
        }
        __syncthreads();
        // build Ast from xs (with left/right zero pad)
        for (int idx = tid; idx < 1152; idx += 256) {
            const int m = idx / 9, k = idx - m * 9;
            const int di = k / 3, dj = k - di * 3 - 1;
            const int rr = (m >> 5) + di;
            const int jj = (m & 31) + dj;
            Ast[k * 128 + m] = (jj >= 0 && jj < 32) ? xs[rr * 32 + jj] : 0.f;
        }
        __syncthreads();
#pragma unroll
        for (int kk = 0; kk < 9; kk++) {
            float a[8], b[8];
            *(float4*)(a)     = *(const float4*)&Ast[kk * 128 + ty * 8];
            *(float4*)(a + 4) = *(const float4*)&Ast[kk * 128 + ty * 8 + 4];
            *(float4*)(b)     = *(const float4*)&Bs [kk * 128 + tx * 8];
            *(float4*)(b + 4) = *(const float4*)&Bs [kk * 128 + tx * 8 + 4];
#pragma unroll
            for (int i = 0; i < 8; i++)
#pragma unroll
                for (int j = 0; j < 8; j++) acc[i][j] += a[i] * b[j];
        }
        __syncthreads();
    }

#pragma unroll
    for (int i = 0; i < 8; i++) {
        const size_t row = (size_t)(p0 + ty * 8 + i) * BA + ba;
        *(float4*)(out + row * D_MOD + n0 + tx * 8)     = *(float4*)(acc[i]);
        *(float4*)(out + row * D_MOD + n0 + tx * 8 + 4) = *(float4*)(acc[i] + 4);
    }
}

// ---------------------------------------------------------------------------
// LayerNorm over D=256 (one block per row, one element per thread).
// Optionally adds `addsrc` (used to fuse spa_token + spa_PE).
// ---------------------------------------------------------------------------
__global__ __launch_bounds__(256) void ln_kernel(
    const float* __restrict__ X, const float* __restrict__ addsrc,
    const float* __restrict__ g, const float* __restrict__ b,
    float* __restrict__ out)
{
    const size_t row = blockIdx.x;
    const int tid = threadIdx.x;
    __shared__ float red[8];

    float v = X[row * D_MOD + tid];
    if (addsrc) v += addsrc[row * D_MOD + tid];

    float s = v;
#pragma unroll
    for (int o = 16; o; o >>= 1) s += __shfl_xor_sync(0xffffffffu, s, o);
    if ((tid & 31) == 0) red[tid >> 5] = s;
    __syncthreads();
    float mean = 0.f;
#pragma unroll
    for (int i = 0; i < 8; i++) mean += red[i];
    mean *= (1.f / 256.f);
    __syncthreads();

    const float dev = v - mean;
    float q = dev * dev;
#pragma unroll
    for (int o = 16; o; o >>= 1) q += __shfl_xor_sync(0xffffffffu, q, o);
    if ((tid & 31) == 0) red[tid >> 5] = q;
    __syncthreads();
    float var = 0.f;
#pragma unroll
    for (int i = 0; i < 8; i++) var += red[i];
    var *= (1.f / 256.f);

    out[row * D_MOD + tid] = dev * rsqrtf(var + 1e-5f) * g[tid] + b[tid];
}

// ---------------------------------------------------------------------------
// Fused attention: one CTA per pixel-batch bq (B=1024).
// K/V tiles [100][256] resident in smem; per query n: scores -> talking-heads
// mix (Wl,bl) -> softmax -> mix (Ww,bw) -> attnscale(lamb) -> AV.
// ---------------------------------------------------------------------------
#define ATT_SMEM_FLOATS (25600 + 25600 + 256 + 800 + 800 + 64 + 64 + 8 + 8 + 8)
#define ATT_SMEM_BYTES  (ATT_SMEM_FLOATS * 4)

__global__ __launch_bounds__(256) void attn_kernel(
    const float* __restrict__ qkv, float* __restrict__ out,
    const float* __restrict__ Wl, const float* __restrict__ bl,
    const float* __restrict__ Ww, const float* __restrict__ bw,
    const float* __restrict__ lamb)
{
    extern __shared__ float sm[];
    float* Ks   = sm;                // [100][256] (m, h*32+d)
    float* Vs   = Ks + 25600;
    float* qs   = Vs + 25600;        // [256]
    float* sraw = qs + 256;          // [8][100]
    float* satt = sraw + 800;        // [8][100]
    float* swl  = satt + 800;        // [64]
    float* sww  = swl + 64;
    float* sbl  = sww + 64;          // [8]
    float* sbw  = sbl + 8;
    float* slam = sbw + 8;

    const int tid = threadIdx.x;
    const int bq = blockIdx.x;
    const float scale = 0.17677669529663687f;  // 1/sqrt(32)

    if (tid < 64) { swl[tid] = Wl[tid]; sww[tid] = Ww[tid]; }
    if (tid < 8)  { sbl[tid] = bl[tid]; sbw[tid] = bw[tid]; slam[tid] = lamb[tid]; }

    const float* base = qkv + (size_t)bq * BA * QKV_N;
    for (int idx = tid; idx < 25600; idx += 256) {
        const int m = idx >> 8, cc = idx & 255;
        Ks[idx] = base[(size_t)m * QKV_N + 256 + cc];
        Vs[idx] = base[(size_t)m * QKV_N + 512 + cc];
    }
    __syncthreads();

    const int g = tid >> 5, lane = tid & 31;

    for (int n = 0; n < BA; n++) {
        qs[tid] = base[(size_t)n * QKV_N + tid] * scale;
        __syncthreads();

        // raw scores: sraw[h][m] = q_h . k_{h,m}
        for (int e = tid; e < 800; e += 256) {
            const int h = e / 100, m = e - h * 100;
            const float* kp = Ks + m * 256 + h * 32;
            const float* qp = qs + h * 32;
            float d = 0.f;
#pragma unroll
            for (int dd = 0; dd < 32; dd++) d += qp[dd] * kp[dd];
            sraw[e] = d;
        }
        __syncthreads();

        // talking-heads (pre-softmax): satt[g][m] = bl[g] + sum_h sraw[h][m]*Wl[g][h]
        for (int e = tid; e < 800; e += 256) {
            const int gg = e / 100, m = e - gg * 100;
            float s = sbl[gg];
#pragma unroll
            for (int h = 0; h < 8; h++) s += sraw[h * 100 + m] * swl[gg * 8 + h];
            satt[e] = s;
        }
        __syncthreads();

        // softmax over m (warp g owns row g); exp written into sraw
        {
            float mx = -1e30f;
            for (int m = lane; m < 100; m += 32) mx = fmaxf(mx, satt[g * 100 + m]);
#pragma unroll
            for (int o = 16; o; o >>= 1) mx = fmaxf(mx, __shfl_xor_sync(0xffffffffu, mx, o));
            float sum = 0.f;
            for (int m = lane; m < 100; m += 32) {
                const float e2 = __expf(satt[g * 100 + m] - mx);
                sraw[g * 100 + m] = e2;
                sum += e2;
            }
#pragma unroll
            for (int o = 16; o; o >>= 1) sum += __shfl_xor_sync(0xffffffffu, sum, o);
            const float inv = 1.f / sum;
            for (int m = lane; m < 100; m += 32) sraw[g * 100 + m] *= inv;
        }
        __syncthreads();

        // talking-heads (post-softmax) + attnscale
        for (int e = tid; e < 800; e += 256) {
            const int gg = e / 100, m = e - gg * 100;
            float s = sbw[gg];
#pragma unroll
            for (int h = 0; h < 8; h++) s += sraw[h * 100 + m] * sww[gg * 8 + h];
            s = 0.01f + (s - 0.01f) * (1.f + slam[gg]);   // attn_d = 1/N = 0.01
            satt[e] = s;
        }
        __syncthreads();

        // AV: out[g][d] = sum_m satt[g][m] * V[m][g*32+d]
        {
            const int d = lane;
            float o = 0.f;
            const float* vp = Vs + g * 32 + d;
            const float* ap = satt + g * 100;
#pragma unroll 4
            for (int m = 0; m < 100; m++) o += ap[m] * vp[m * 256];
            out[((size_t)bq * BA + n) * D_MOD + g * 32 + d] = o;
        }
        __syncthreads();
    }
}

// ---------------------------------------------------------------------------
// Token2SAI + 1x1x1 conv: out[b_, o, a, i, j] = sum_d F[(p*100+ba), d] * Wc[o, d]
// Block: fixed ba, 128 p x 128 o; writes contiguous in p (coalesced).
// grid = (PIX/128=8, BA=100)
// ---------------------------------------------------------------------------
__global__ __launch_bounds__(256) void t2s_kernel(
    const float* __restrict__ F, const float* __restrict__ Wc,
    float* __restrict__ out)
{
    __shared__ float Wt[8 * 128];   // [k][o]
    __shared__ float Fs[8 * 128];   // [k][p]
    const int tid = threadIdx.x;
    const int p0 = blockIdx.x * 128;
    const int ba = blockIdx.y;
    const int b_ = ba / AA, a_ = ba - b_ * AA;
    const int tx = tid & 15;        // p direction
    const int ty = tid >> 4;        // o direction

    float acc[8][8];
#pragma unroll
    for (int i = 0; i < 8; i++)
#pragma unroll
        for (int j = 0; j < 8; j++) acc[i][j] = 0.f;

    const int wrow = tid >> 1, wcol = (tid & 1) * 4;
    const int frow = tid >> 1, fcol = (tid & 1) * 4;

    for (int k0 = 0; k0 < D_MOD; k0 += 8) {
        float4 wv = *(const float4*)(Wc + (size_t)wrow * D_MOD + k0 + wcol);
        Wt[(wcol + 0) * 128 + wrow] = wv.x;
        Wt[(wcol + 1) * 128 + wrow] = wv.y;
        Wt[(wcol + 2) * 128 + wrow] = wv.z;
        Wt[(wcol + 3) * 128 + wrow] = wv.w;
        float4 fv = *(const float4*)(F + ((size_t)(p0 + frow) * BA + ba) * D_MOD + k0 + fcol);
        Fs[(fcol + 0) * 128 + frow] = fv.x;
        Fs[(fcol + 1) * 128 + frow] = fv.y;
        Fs[(fcol + 2) * 128 + frow] = fv.z;
        Fs[(fcol + 3) * 128 + frow] = fv.w;
        __syncthreads();
#pragma unroll
        for (int kk = 0; kk < 8; kk++) {
            float a[8], b[8];
            *(float4*)(a)     = *(const float4*)&Wt[kk * 128 + ty * 8];
            *(float4*)(a + 4) = *(const float4*)&Wt[kk * 128 + ty * 8 + 4];
            *(float4*)(b)     = *(const float4*)&Fs[kk * 128 + tx * 8];
            *(float4*)(b + 4) = *(const float4*)&Fs[kk * 128 + tx * 8 + 4];
#pragma unroll
            for (int i = 0; i < 8; i++)
#pragma unroll
                for (int j = 0; j < 8; j++) acc[i][j] += a[i] * b[j];
        }
        __syncthreads();
    }

#pragma unroll
    for (int i = 0; i < 8; i++) {
        const int o = ty * 8 + i;
        float* op = out + ((size_t)(b_ * CCH + o) * AA + a_) * PIX + p0 + tx * 8;
        *(float4*)(op)     = *(float4*)(acc[i]);
        *(float4*)(op + 4) = *(float4*)(acc[i] + 4);
    }
}

// ---------------------------------------------------------------------------
extern "C" void kernel_launch(void* const* d_in, const int* in_sizes, int n_in,
                              void* d_out, int out_size)
{
    const float* buffer  = (const float*)d_in[0];
    const float* spa_pos = (const float*)d_in[1];
    const float* W_mlp   = (const float*)d_in[2];
    const float* g1      = (const float*)d_in[3];
    const float* b1      = (const float*)d_in[4];
    const float* Wqkv    = (const float*)d_in[5];
    const float* Wproj   = (const float*)d_in[6];
    const float* bproj   = (const float*)d_in[7];
    const float* Wl      = (const float*)d_in[8];
    const float* bl      = (const float*)d_in[9];
    const float* Ww      = (const float*)d_in[10];
    const float* bw      = (const float*)d_in[11];
    const float* lamb    = (const float*)d_in[12];
    const float* g2      = (const float*)d_in[13];
    const float* b2      = (const float*)d_in[14];
    const float* W1      = (const float*)d_in[15];
    const float* W2      = (const float*)d_in[16];
    const float* Wconv   = (const float*)d_in[17];
    float* out = (float*)d_out;

    float *T, *PE, *X, *QKV, *AO, *S2, *Y, *FF1;
    cudaGetSymbolAddress((void**)&T,   g_T);
    cudaGetSymbolAddress((void**)&PE,  g_PE);
    cudaGetSymbolAddress((void**)&X,   g_X);
    cudaGetSymbolAddress((void**)&QKV, g_QKV);
    cudaGetSymbolAddress((void**)&AO,  g_AO);
    cudaGetSymbolAddress((void**)&S2,  g_S2);
    cudaGetSymbolAddress((void**)&Y,   g_Y);
    cudaGetSymbolAddress((void**)&FF1, g_FF1);

    cudaFuncSetAttribute(attn_kernel, cudaFuncAttributeMaxDynamicSharedMemorySize,
                         ATT_SMEM_BYTES);

    // 1) sai2token on buffer and on spa_position (linearity: PE-add fused in LN1)
    dim3 cg(D_MOD / 128, PIX / 128, BA);
    conv_kernel<<<cg, 256>>>(buffer,  W_mlp, T);
    conv_kernel<<<cg, 256>>>(spa_pos, W_mlp, PE);

    // 2) x = LN(T + PE)
    ln_kernel<<<TOK_M, 256>>>(T, PE, g1, b1, X);

    // 3) qkv = x @ Wqkv
    sgemm128<<<dim3(QKV_N / 128, TOK_M / 128), 256>>>(X, Wqkv, QKV,
        TOK_M, QKV_N, D_MOD, nullptr, nullptr, 0);

    // 4) fused attention core
    attn_kernel<<<PIX, 256, ATT_SMEM_BYTES>>>(QKV, AO, Wl, bl, Ww, bw, lamb);

    // 5) S2 = AO @ Wproj + bproj + T
    sgemm128<<<dim3(D_MOD / 128, TOK_M / 128), 256>>>(AO, Wproj, S2,
        TOK_M, D_MOD, D_MOD, bproj, T, 0);

    // 6) y = LN(S2)
    ln_kernel<<<TOK_M, 256>>>(S2, nullptr, g2, b2, Y);

    // 7) FF1 = relu(y @ W1);  final = FF1 @ W2 + S2  (reuse X as final)
    sgemm128<<<dim3(D_FF / 128, TOK_M / 128), 256>>>(Y, W1, FF1,
        TOK_M, D_FF, D_MOD, nullptr, nullptr, 1);
    sgemm128<<<dim3(D_MOD / 128, TOK_M / 128), 256>>>(FF1, W2, X,
        TOK_M, D_MOD, D_FF, nullptr, S2, 0);

    // 8) Token2SAI + 1x1x1 conv -> out
    t2s_kernel<<<dim3(PIX / 128, BA), 256>>>(X, Wconv, out);
}

// round 3
// speedup vs baseline: 1.1509x; 1.1509x over previous
#include <cuda_runtime.h>
#include <math.h>

// ---------------------------------------------------------------------------
// Problem constants: b=4, c=128, a=25, h=w=32
//   tokens: M = 1024*100 = 102400, D = 256
//   attention: B = 1024 pixels, N = 100, H = 8, hd = 32
// ---------------------------------------------------------------------------
#define TOK_M   102400
#define D_MOD   256
#define D_FF    512
#define QKV_N   768
#define BA      100
#define PIX     1024
#define CCH     128
#define AA      25

// ------------------------- scratch (static device) -------------------------
__device__ float g_T  [TOK_M * D_MOD];
__device__ float g_PE [TOK_M * D_MOD];
__device__ float g_X  [TOK_M * D_MOD];
__device__ float g_QKV[TOK_M * QKV_N];
__device__ float g_AO [TOK_M * D_MOD];
__device__ float g_S2 [TOK_M * D_MOD];
__device__ float g_Y  [TOK_M * D_MOD];
__device__ float g_FF1[TOK_M * D_FF];

// ---------------------------------------------------------------------------
// SGEMM v2: C[M,N] = A[M,K] @ B[K,N] (+bias)(+relu)(+resid)
// BM=BN=128, BK=16, 256 threads, 8x8 micro-tile, double-buffered smem,
// one __syncthreads per k-tile.
// ---------------------------------------------------------------------------
__global__ __launch_bounds__(256) void sgemm_v2(
    const float* __restrict__ A, const float* __restrict__ B,
    float* __restrict__ C, int M, int N, int K,
    const float* __restrict__ bias, const float* __restrict__ resid, int relu)
{
    __shared__ float As[2][16 * 128];   // [k][m]
    __shared__ float Bs[2][16 * 128];   // [k][n]
    const int tid = threadIdx.x;
    const int m0 = blockIdx.y * 128;
    const int n0 = blockIdx.x * 128;
    const int tx = tid & 15;            // n direction
    const int ty = tid >> 4;            // m direction

    const int rowA = tid >> 2;          // 0..63 (and +64)
    const int c4   = (tid & 3) * 4;     // k offset within tile
    const int rowB = tid >> 5;          // 0..7 (and +8)
    const int colB = (tid & 31) * 4;

    const float* Ap0 = A + (size_t)(m0 + rowA) * K + c4;
    const float* Ap1 = A + (size_t)(m0 + rowA + 64) * K + c4;
    const float* Bp0 = B + (size_t)rowB * N + n0 + colB;
    const float* Bp1 = B + (size_t)(rowB + 8) * N + n0 + colB;

    float acc[8][8];
#pragma unroll
    for (int i = 0; i < 8; i++)
#pragma unroll
        for (int j = 0; j < 8; j++) acc[i][j] = 0.f;

    const int nt = K >> 4;

    // prologue: tile 0 -> buf 0
    {
        float4 a0 = *(const float4*)(Ap0);
        float4 a1 = *(const float4*)(Ap1);
        float4 b0 = *(const float4*)(Bp0);
        float4 b1 = *(const float4*)(Bp1);
        As[0][(c4 + 0) * 128 + rowA] = a0.x;
        As[0][(c4 + 1) * 128 + rowA] = a0.y;
        As[0][(c4 + 2) * 128 + rowA] = a0.z;
        As[0][(c4 + 3) * 128 + rowA] = a0.w;
        As[0][(c4 + 0) * 128 + rowA + 64] = a1.x;
        As[0][(c4 + 1) * 128 + rowA + 64] = a1.y;
        As[0][(c4 + 2) * 128 + rowA + 64] = a1.z;
        As[0][(c4 + 3) * 128 + rowA + 64] = a1.w;
        *(float4*)&Bs[0][rowB * 128 + colB]       = b0;
        *(float4*)&Bs[0][(rowB + 8) * 128 + colB] = b1;
    }
    __syncthreads();

    for (int t = 0; t < nt; t++) {
        const int cur = t & 1;
        float4 a0, a1, b0, b1;
        const bool more = (t + 1 < nt);
        if (more) {
            const size_t ko = (size_t)(t + 1) * 16;
            a0 = *(const float4*)(Ap0 + ko);
            a1 = *(const float4*)(Ap1 + ko);
            b0 = *(const float4*)(Bp0 + ko * N);
            b1 = *(const float4*)(Bp1 + ko * N);
        }
        const float* Ac = As[cur];
        const float* Bc = Bs[cur];
#pragma unroll
        for (int kk = 0; kk < 16; kk++) {
            float a[8], b[8];
            *(float4*)(a)     = *(const float4*)&Ac[kk * 128 + ty * 8];
            *(float4*)(a + 4) = *(const float4*)&Ac[kk * 128 + ty * 8 + 4];
            *(float4*)(b)     = *(const float4*)&Bc[kk * 128 + tx * 8];
            *(float4*)(b + 4) = *(const float4*)&Bc[kk * 128 + tx * 8 + 4];
#pragma unroll
            for (int i = 0; i < 8; i++)
#pragma unroll
                for (int j = 0; j < 8; j++) acc[i][j] += a[i] * b[j];
        }
        if (more) {
            const int alt = cur ^ 1;
            As[alt][(c4 + 0) * 128 + rowA] = a0.x;
            As[alt][(c4 + 1) * 128 + rowA] = a0.y;
            As[alt][(c4 + 2) * 128 + rowA] = a0.z;
            As[alt][(c4 + 3) * 128 + rowA] = a0.w;
            As[alt][(c4 + 0) * 128 + rowA + 64] = a1.x;
            As[alt][(c4 + 1) * 128 + rowA + 64] = a1.y;
            As[alt][(c4 + 2) * 128 + rowA + 64] = a1.z;
            As[alt][(c4 + 3) * 128 + rowA + 64] = a1.w;
            *(float4*)&Bs[alt][rowB * 128 + colB]       = b0;
            *(float4*)&Bs[alt][(rowB + 8) * 128 + colB] = b1;
        }
        __syncthreads();
    }

#pragma unroll
    for (int i = 0; i < 8; i++) {
        const int m = m0 + ty * 8 + i;
        float v[8];
#pragma unroll
        for (int j = 0; j < 8; j++) {
            const int n = n0 + tx * 8 + j;
            float x = acc[i][j];
            if (bias)  x += bias[n];
            if (relu)  x = fmaxf(x, 0.f);
            if (resid) x += resid[(size_t)m * N + n];
            v[j] = x;
        }
        *(float4*)(C + (size_t)m * N + n0 + tx * 8)     = *(float4*)(v);
        *(float4*)(C + (size_t)m * N + n0 + tx * 8 + 4) = *(float4*)(v + 4);
    }
}

// ---------------------------------------------------------------------------
// sai2token conv v2 (implicit im2col, register-window taps).
// Block: fixed ba, 128 pixels (4 image rows) x 128 d. Each thread owns 8
// consecutive pixels of ONE image row -> 3x10 register window feeds 9 taps.
// xs/Bs double-buffered, 1 sync/channel. grid = (2, 8, 100)
// ---------------------------------------------------------------------------
__global__ __launch_bounds__(256) void conv_v2(
    const float* __restrict__ src, const float* __restrict__ W,
    float* __restrict__ out)
{
    __shared__ float xs[2][6 * 32];
    __shared__ float Bs[2][9 * 128];
    const int tid = threadIdx.x;
    const int n0 = blockIdx.x * 128;
    const int p0 = blockIdx.y * 128;
    const int ba = blockIdx.z;
    const int b_ = ba / AA, a_ = ba - b_ * AA;
    const int i0 = p0 >> 5;
    const int tx = tid & 15, ty = tid >> 4;
    const int rr  = ty >> 2;
    const int jj0 = (ty & 3) * 8;

    float acc[8][8];
#pragma unroll
    for (int i = 0; i < 8; i++)
#pragma unroll
        for (int j = 0; j < 8; j++) acc[i][j] = 0.f;

    const float* srcb = src + ((size_t)(b_ * CCH) * AA + a_) * PIX;
    const size_t cstr = (size_t)AA * PIX;

    const int xr = tid >> 5, xj = tid & 31;
    const int xi = i0 - 1 + xr;
    const bool xok = (tid < 192) && (xi >= 0) && (xi < 32);
    const float* xptr = srcb + (size_t)xi * 32 + xj;

    const int bk0 = tid >> 5, bn0 = (tid & 31) * 4;
    const float* Wb = W + n0;

    // prologue: channel 0 -> buf 0
    {
        if (tid < 192) xs[0][tid] = xok ? xptr[0] : 0.f;
        float4 w0 = *(const float4*)(Wb + (size_t)bk0 * D_MOD + bn0);
        *(float4*)&Bs[0][bk0 * 128 + bn0] = w0;
        if (tid < 32) {
            float4 w1 = *(const float4*)(Wb + (size_t)8 * D_MOD + tid * 4);  // FIXED
            *(float4*)&Bs[0][8 * 128 + tid * 4] = w1;
        }
    }
    __syncthreads();

    for (int c = 0; c < CCH; c++) {
        const int cur = c & 1;
        const bool more = (c + 1 < CCH);
        float xnext = 0.f;
        float4 w0, w1;
        if (more) {
            if (tid < 192 && xok) xnext = xptr[(size_t)(c + 1) * cstr];
            const float* Wc = W + (size_t)(c + 1) * 9 * D_MOD + n0;
            w0 = *(const float4*)(Wc + (size_t)bk0 * D_MOD + bn0);
            if (tid < 32)
                w1 = *(const float4*)(Wc + (size_t)8 * D_MOD + tid * 4);
        }

        float win[3][10];
        const float* xc = xs[cur];
#pragma unroll
        for (int r = 0; r < 3; r++) {
            const float* rowp = xc + (rr + r) * 32;
#pragma unroll
            for (int q = 0; q < 10; q++) {
                const int jj = jj0 - 1 + q;
                win[r][q] = (jj >= 0 && jj < 32) ? rowp[jj] : 0.f;
            }
        }

        const float* Bc = Bs[cur];
#pragma unroll
        for (int di = 0; di < 3; di++) {
#pragma unroll
            for (int dj = 0; dj < 3; dj++) {
                const int k = di * 3 + dj;
                float b[8];
                *(float4*)(b)     = *(const float4*)&Bc[k * 128 + tx * 8];
                *(float4*)(b + 4) = *(const float4*)&Bc[k * 128 + tx * 8 + 4];
#pragma unroll
                for (int i = 0; i < 8; i++) {
                    const float a = win[di][i + dj];
#pragma unroll
                    for (int j = 0; j < 8; j++) acc[i][j] += a * b[j];
                }
            }
        }

        if (more) {
            const int alt = cur ^ 1;
            if (tid < 192) xs[alt][tid] = xnext;
            *(float4*)&Bs[alt][bk0 * 128 + bn0] = w0;
            if (tid < 32) *(float4*)&Bs[alt][8 * 128 + tid * 4] = w1;
        }
        __syncthreads();
    }

#pragma unroll
    for (int i = 0; i < 8; i++) {
        const size_t row = (size_t)(p0 + ty * 8 + i) * BA + ba;
        *(float4*)(out + row * D_MOD + n0 + tx * 8)     = *(float4*)(acc[i]);
        *(float4*)(out + row * D_MOD + n0 + tx * 8 + 4) = *(float4*)(acc[i] + 4);
    }
}

// ---------------------------------------------------------------------------
// LayerNorm over D=256 (one block/row). Optionally adds addsrc.
// ---------------------------------------------------------------------------
__global__ __launch_bounds__(256) void ln_kernel(
    const float* __restrict__ X, const float* __restrict__ addsrc,
    const float* __restrict__ g, const float* __restrict__ b,
    float* __restrict__ out)
{
    const size_t row = blockIdx.x;
    const int tid = threadIdx.x;
    __shared__ float red[8];

    float v = X[row * D_MOD + tid];
    if (addsrc) v += addsrc[row * D_MOD + tid];

    float s = v;
#pragma unroll
    for (int o = 16; o; o >>= 1) s += __shfl_xor_sync(0xffffffffu, s, o);
    if ((tid & 31) == 0) red[tid >> 5] = s;
    __syncthreads();
    float mean = 0.f;
#pragma unroll
    for (int i = 0; i < 8; i++) mean += red[i];
    mean *= (1.f / 256.f);
    __syncthreads();

    const float dev = v - mean;
    float q = dev * dev;
#pragma unroll
    for (int o = 16; o; o >>= 1) q += __shfl_xor_sync(0xffffffffu, q, o);
    if ((tid & 31) == 0) red[tid >> 5] = q;
    __syncthreads();
    float var = 0.f;
#pragma unroll
    for (int i = 0; i < 8; i++) var += red[i];
    var *= (1.f / 256.f);

    out[row * D_MOD + tid] = dev * rsqrtf(var + 1e-5f) * g[tid] + b[tid];
}

// ---------------------------------------------------------------------------
// Fused attention: one CTA per pixel bq.
// ---------------------------------------------------------------------------
#define ATT_SMEM_FLOATS (25600 + 25600 + 256 + 800 + 800 + 64 + 64 + 8 + 8 + 8)
#define ATT_SMEM_BYTES  (ATT_SMEM_FLOATS * 4)

__global__ __launch_bounds__(256) void attn_kernel(
    const float* __restrict__ qkv, float* __restrict__ out,
    const float* __restrict__ Wl, const float* __restrict__ bl,
    const float* __restrict__ Ww, const float* __restrict__ bw,
    const float* __restrict__ lamb)
{
    extern __shared__ float sm[];
    float* Ks   = sm;
    float* Vs   = Ks + 25600;
    float* qs   = Vs + 25600;
    float* sraw = qs + 256;
    float* satt = sraw + 800;
    float* swl  = satt + 800;
    float* sww  = swl + 64;
    float* sbl  = sww + 64;
    float* sbw  = sbl + 8;
    float* slam = sbw + 8;

    const int tid = threadIdx.x;
    const int bq = blockIdx.x;
    const float scale = 0.17677669529663687f;

    if (tid < 64) { swl[tid] = Wl[tid]; sww[tid] = Ww[tid]; }
    if (tid < 8)  { sbl[tid] = bl[tid]; sbw[tid] = bw[tid]; slam[tid] = lamb[tid]; }

    const float* base = qkv + (size_t)bq * BA * QKV_N;
    for (int idx = tid; idx < 25600; idx += 256) {
        const int m = idx >> 8, cc = idx & 255;
        Ks[idx] = base[(size_t)m * QKV_N + 256 + cc];
        Vs[idx] = base[(size_t)m * QKV_N + 512 + cc];
    }
    __syncthreads();

    const int g = tid >> 5, lane = tid & 31;

    for (int n = 0; n < BA; n++) {
        qs[tid] = base[(size_t)n * QKV_N + tid] * scale;
        __syncthreads();

        for (int e = tid; e < 800; e += 256) {
            const int h = e / 100, m = e - h * 100;
            const float* kp = Ks + m * 256 + h * 32;
            const float* qp = qs + h * 32;
            float d = 0.f;
#pragma unroll
            for (int dd = 0; dd < 32; dd++) d += qp[dd] * kp[dd];
            sraw[e] = d;
        }
        __syncthreads();

        for (int e = tid; e < 800; e += 256) {
            const int gg = e / 100, m = e - gg * 100;
            float s = sbl[gg];
#pragma unroll
            for (int h = 0; h < 8; h++) s += sraw[h * 100 + m] * swl[gg * 8 + h];
            satt[e] = s;
        }
        __syncthreads();

        {
            float mx = -1e30f;
            for (int m = lane; m < 100; m += 32) mx = fmaxf(mx, satt[g * 100 + m]);
#pragma unroll
            for (int o = 16; o; o >>= 1) mx = fmaxf(mx, __shfl_xor_sync(0xffffffffu, mx, o));
            float sum = 0.f;
            for (int m = lane; m < 100; m += 32) {
                const float e2 = __expf(satt[g * 100 + m] - mx);
                sraw[g * 100 + m] = e2;
                sum += e2;
            }
#pragma unroll
            for (int o = 16; o; o >>= 1) sum += __shfl_xor_sync(0xffffffffu, sum, o);
            const float inv = 1.f / sum;
            for (int m = lane; m < 100; m += 32) sraw[g * 100 + m] *= inv;
        }
        __syncthreads();

        for (int e = tid; e < 800; e += 256) {
            const int gg = e / 100, m = e - gg * 100;
            float s = sbw[gg];
#pragma unroll
            for (int h = 0; h < 8; h++) s += sraw[h * 100 + m] * sww[gg * 8 + h];
            s = 0.01f + (s - 0.01f) * (1.f + slam[gg]);
            satt[e] = s;
        }
        __syncthreads();

        {
            const int d = lane;
            float o = 0.f;
            const float* vp = Vs + g * 32 + d;
            const float* ap = satt + g * 100;
#pragma unroll 4
            for (int m = 0; m < 100; m++) o += ap[m] * vp[m * 256];
            out[((size_t)bq * BA + n) * D_MOD + g * 32 + d] = o;
        }
        __syncthreads();
    }
}

// ---------------------------------------------------------------------------
// Token2SAI + 1x1x1 conv
// ---------------------------------------------------------------------------
__global__ __launch_bounds__(256) void t2s_kernel(
    const float* __restrict__ F, const float* __restrict__ Wc,
    float* __restrict__ out)
{
    __shared__ float Wt[8 * 128];
    __shared__ float Fs[8 * 128];
    const int tid = threadIdx.x;
    const int p0 = blockIdx.x * 128;
    const int ba = blockIdx.y;
    const int b_ = ba / AA, a_ = ba - b_ * AA;
    const int tx = tid & 15;
    const int ty = tid >> 4;

    float acc[8][8];
#pragma unroll
    for (int i = 0; i < 8; i++)
#pragma unroll
        for (int j = 0; j < 8; j++) acc[i][j] = 0.f;

    const int wrow = tid >> 1, wcol = (tid & 1) * 4;

    for (int k0 = 0; k0 < D_MOD; k0 += 8) {
        float4 wv = *(const float4*)(Wc + (size_t)wrow * D_MOD + k0 + wcol);
        Wt[(wcol + 0) * 128 + wrow] = wv.x;
        Wt[(wcol + 1) * 128 + wrow] = wv.y;
        Wt[(wcol + 2) * 128 + wrow] = wv.z;
        Wt[(wcol + 3) * 128 + wrow] = wv.w;
        float4 fv = *(const float4*)(F + ((size_t)(p0 + wrow) * BA + ba) * D_MOD + k0 + wcol);
        Fs[(wcol + 0) * 128 + wrow] = fv.x;
        Fs[(wcol + 1) * 128 + wrow] = fv.y;
        Fs[(wcol + 2) * 128 + wrow] = fv.z;
        Fs[(wcol + 3) * 128 + wrow] = fv.w;
        __syncthreads();
#pragma unroll
        for (int kk = 0; kk < 8; kk++) {
            float a[8], b[8];
            *(float4*)(a)     = *(const float4*)&Wt[kk * 128 + ty * 8];
            *(float4*)(a + 4) = *(const float4*)&Wt[kk * 128 + ty * 8 + 4];
            *(float4*)(b)     = *(const float4*)&Fs[kk * 128 + tx * 8];
            *(float4*)(b + 4) = *(const float4*)&Fs[kk * 128 + tx * 8 + 4];
#pragma unroll
            for (int i = 0; i < 8; i++)
#pragma unroll
                for (int j = 0; j < 8; j++) acc[i][j] += a[i] * b[j];
        }
        __syncthreads();
    }

#pragma unroll
    for (int i = 0; i < 8; i++) {
        const int o = ty * 8 + i;
        float* op = out + ((size_t)(b_ * CCH + o) * AA + a_) * PIX + p0 + tx * 8;
        *(float4*)(op)     = *(float4*)(acc[i]);
        *(float4*)(op + 4) = *(float4*)(acc[i] + 4);
    }
}

// ---------------------------------------------------------------------------
extern "C" void kernel_launch(void* const* d_in, const int* in_sizes, int n_in,
                              void* d_out, int out_size)
{
    const float* buffer  = (const float*)d_in[0];
    const float* spa_pos = (const float*)d_in[1];
    const float* W_mlp   = (const float*)d_in[2];
    const float* g1      = (const float*)d_in[3];
    const float* b1      = (const float*)d_in[4];
    const float* Wqkv    = (const float*)d_in[5];
    const float* Wproj   = (const float*)d_in[6];
    const float* bproj   = (const float*)d_in[7];
    const float* Wl      = (const float*)d_in[8];
    const float* bl      = (const float*)d_in[9];
    const float* Ww      = (const float*)d_in[10];
    const float* bw      = (const float*)d_in[11];
    const float* lamb    = (const float*)d_in[12];
    const float* g2      = (const float*)d_in[13];
    const float* b2      = (const float*)d_in[14];
    const float* W1      = (const float*)d_in[15];
    const float* W2      = (const float*)d_in[16];
    const float* Wconv   = (const float*)d_in[17];
    float* out = (float*)d_out;

    float *T, *PE, *X, *QKV, *AO, *S2, *Y, *FF1;
    cudaGetSymbolAddress((void**)&T,   g_T);
    cudaGetSymbolAddress((void**)&PE,  g_PE);
    cudaGetSymbolAddress((void**)&X,   g_X);
    cudaGetSymbolAddress((void**)&QKV, g_QKV);
    cudaGetSymbolAddress((void**)&AO,  g_AO);
    cudaGetSymbolAddress((void**)&S2,  g_S2);
    cudaGetSymbolAddress((void**)&Y,   g_Y);
    cudaGetSymbolAddress((void**)&FF1, g_FF1);

    cudaFuncSetAttribute(attn_kernel, cudaFuncAttributeMaxDynamicSharedMemorySize,
                         ATT_SMEM_BYTES);

    dim3 cg(D_MOD / 128, PIX / 128, BA);
    conv_v2<<<cg, 256>>>(buffer,  W_mlp, T);
    conv_v2<<<cg, 256>>>(spa_pos, W_mlp, PE);

    ln_kernel<<<TOK_M, 256>>>(T, PE, g1, b1, X);

    sgemm_v2<<<dim3(QKV_N / 128, TOK_M / 128), 256>>>(X, Wqkv, QKV,
        TOK_M, QKV_N, D_MOD, nullptr, nullptr, 0);

    attn_kernel<<<PIX, 256, ATT_SMEM_BYTES>>>(QKV, AO, Wl, bl, Ww, bw, lamb);

    sgemm_v2<<<dim3(D_MOD / 128, TOK_M / 128), 256>>>(AO, Wproj, S2,
        TOK_M, D_MOD, D_MOD, bproj, T, 0);

    ln_kernel<<<TOK_M, 256>>>(S2, nullptr, g2, b2, Y);

    sgemm_v2<<<dim3(D_FF / 128, TOK_M / 128), 256>>>(Y, W1, FF1,
        TOK_M, D_FF, D_MOD, nullptr, nullptr, 1);
    sgemm_v2<<<dim3(D_MOD / 128, TOK_M / 128), 256>>>(FF1, W2, X,
        TOK_M, D_MOD, D_FF, nullptr, S2, 0);

    t2s_kernel<<<dim3(PIX / 128, BA), 256>>>(X, Wconv, out);
}